// round 14
// baseline (speedup 1.0000x reference)
#include <cuda_runtime.h>
#include <cstdint>

#define N_ROWS   2048
#define DDIM     256
#define T_TRACKS 256
#define NY       16384
#define NTOT     18432
#define BM       128
#define BN       128
#define KC       64
#define NCH      (DDIM / KC)           // 4
#define NSTAGE   3
#define INV_TEMP (1.0f / 0.3f)

#define A_BYTES  (BM * 128)            // 16384
#define B_BYTES  (BN * 128)            // 16384
#define STAGE    (A_BYTES + B_BYTES)   // 32768
#define SMEM_DYN (NSTAGE * STAGE + 1024)   // 99328 -> 2 CTAs/SM
#define NBLOCKS  ((N_ROWS / BM) * (NTOT / BN))   // 2304

// Scratch (zero at module load; fused finalize self-cleans each replay)
__device__ float    g_rxy_tot[N_ROWS];
__device__ float    g_rxy_pos[N_ROWS];
__device__ float    g_rxx_tot[N_ROWS];
__device__ float    g_rxx_pos[N_ROWS];
__device__ float    g_diag[N_ROWS];
__device__ unsigned g_ctr;
// bf16 copies of inputs (bf16x2 packed, k-contiguous), rebuilt every call
__device__ unsigned g_xb[N_ROWS * DDIM / 2];
__device__ unsigned g_yb[NY * DDIM / 2];

__device__ __forceinline__ uint32_t smem_u32(const void* p) {
    uint32_t a;
    asm("{ .reg .u64 t; cvta.to.shared.u64 t, %1; cvt.u32.u64 %0, t; }" : "=r"(a) : "l"(p));
    return a;
}
__device__ __forceinline__ unsigned pk(float hi, float lo) {
    unsigned r;
    asm("cvt.rn.bf16x2.f32 %0, %1, %2;" : "=r"(r) : "f"(hi), "f"(lo));
    return r;
}
__device__ __forceinline__ uint32_t swz(uint32_t off) {
    return off ^ ((off >> 3) & 0x70);
}
__device__ __forceinline__ void cpasync16(uint32_t dst, const void* src) {
    asm volatile("cp.async.ca.shared.global [%0], [%1], 16;" :: "r"(dst), "l"(src));
}
#define CP_COMMIT() asm volatile("cp.async.commit_group;" ::: "memory")
#define CP_WAIT(N)  asm volatile("cp.async.wait_group %0;" :: "n"(N) : "memory")
__device__ __forceinline__ void ldsm4(unsigned* r, uint32_t addr) {
    asm volatile("ldmatrix.sync.aligned.m8n8.x4.shared.b16 {%0,%1,%2,%3}, [%4];"
                 : "=r"(r[0]), "=r"(r[1]), "=r"(r[2]), "=r"(r[3]) : "r"(addr));
}
__device__ __forceinline__ void mma_bf16(float* c, const unsigned* a, const unsigned* b) {
    asm volatile(
        "mma.sync.aligned.m16n8k16.row.col.f32.bf16.bf16.f32 "
        "{%0,%1,%2,%3}, {%4,%5,%6,%7}, {%8,%9}, {%0,%1,%2,%3};"
        : "+f"(c[0]), "+f"(c[1]), "+f"(c[2]), "+f"(c[3])
        : "r"(a[0]), "r"(a[1]), "r"(a[2]), "r"(a[3]), "r"(b[0]), "r"(b[1]));
}

// fp32 -> bf16x2: branch-free block partition, 4 independent float4 loads/thread
__global__ void conv_kernel(const float4* __restrict__ x4, const float4* __restrict__ y4) {
    int b = blockIdx.x;
    const float4* src;
    uint2* dst;
    if (b < 128) { src = x4; dst = (uint2*)g_xb; }                 // 128*1024 = 131072 items
    else         { src = y4; dst = (uint2*)g_yb; b -= 128; }       // 1024*1024 items
    const int i0 = b * 1024 + threadIdx.x;
    float4 v[4];
#pragma unroll
    for (int k = 0; k < 4; k++) v[k] = src[i0 + k * 256];
#pragma unroll
    for (int k = 0; k < 4; k++) {
        uint2 r;
        r.x = pk(v[k].y, v[k].x);
        r.y = pk(v[k].w, v[k].z);
        dst[i0 + k * 256] = r;
    }
}

__global__ __launch_bounds__(256, 2) void sim_kernel(const int* __restrict__ tid,
                                                     float* __restrict__ out) {
    extern __shared__ char dynsm[];
    __shared__ int labs[BN];
    __shared__ int lastFlag;

    const int t    = threadIdx.x;
    const int lane = t & 31;
    const int w    = t >> 5;        // 8 warps
    const int wm   = w >> 2;        // 0..1  (64 rows each)
    const int wn   = w & 3;         // 0..3  (32 cols each)
    const int g    = lane >> 2;     // 0..7
    const int tq   = lane & 3;      // 0..3

    const int rowBase = blockIdx.x * BM;
    const int colBase = blockIdx.y * BN;
    const bool is_xx  = (colBase >= NY);
    const char* asrc = (const char*)g_xb + (size_t)rowBase * 512;   // 512B per row
    const char* bsrc = is_xx ? ((const char*)g_xb + (size_t)(colBase - NY) * 512)
                             : ((const char*)g_yb + (size_t)colBase * 512);

    uint32_t sb  = smem_u32(dynsm);
    uint32_t pad = (1024u - (sb & 1023u)) & 1023u;
    const uint32_t baseAddr = sb + pad;

    if (t < BN) {   // labels for this tile's columns
        const int gcol = colBase + t;
        labs[t] = is_xx ? tid[gcol - NY] : (gcol & (T_TRACKS - 1));
    }

    // cp.async granule mapping: A and B each 1024 granules -> 4 per thread
    int arow_[4], akq_[4];
    uint32_t adst_[4];
#pragma unroll
    for (int i = 0; i < 4; i++) {
        const int idx = t + i * 256;
        arow_[i] = idx >> 3; akq_[i] = idx & 7;
        adst_[i] = swz((uint32_t)(arow_[i] * 128 + akq_[i] * 16));
    }

    auto issue_chunk = [&](int ch, int stg) {
        const uint32_t sA = baseAddr + stg * STAGE;
        const uint32_t sB = sA + A_BYTES;
#pragma unroll
        for (int i = 0; i < 4; i++)
            cpasync16(sA + adst_[i], asrc + (size_t)arow_[i] * 512 + ch * 128 + akq_[i] * 16);
#pragma unroll
        for (int i = 0; i < 4; i++)
            cpasync16(sB + adst_[i], bsrc + (size_t)arow_[i] * 512 + ch * 128 + akq_[i] * 16);
        CP_COMMIT();
    };

    // ldmatrix base offsets (s=0); k-step applied as XOR (s<<5) — exact under SW128
    uint32_t aoffB[4], boffB[2];
    {
        const int rA = lane & 15;
        const int kA = (lane >> 4) * 16;
#pragma unroll
        for (int mt = 0; mt < 4; mt++)
            aoffB[mt] = swz((uint32_t)((wm * 64 + mt * 16 + rA) * 128 + kA));
        const int rB = (lane & 7) + (lane >> 4) * 8;
        const int kB = ((lane >> 3) & 1) * 16;
#pragma unroll
        for (int p = 0; p < 2; p++)
            boffB[p] = swz((uint32_t)((wn * 32 + p * 16 + rB) * 128 + kB));
    }

    float c[4][4][4];
#pragma unroll
    for (int mt = 0; mt < 4; mt++)
#pragma unroll
        for (int nt = 0; nt < 4; nt++)
#pragma unroll
            for (int q = 0; q < 4; q++) c[mt][nt][q] = 0.f;

    issue_chunk(0, 0);
    issue_chunk(1, 1);

#pragma unroll
    for (int ch = 0; ch < NCH; ch++) {
        if (ch < NCH - 1) CP_WAIT(1); else CP_WAIT(0);
        __syncthreads();
        if (ch + 2 < NCH) issue_chunk(ch + 2, (ch + 2) % NSTAGE);

        const uint32_t aAdr = baseAddr + (ch % NSTAGE) * STAGE;
        const uint32_t bAdr = aAdr + A_BYTES;
#pragma unroll
        for (int s = 0; s < 4; s++) {
            const uint32_t sx = (uint32_t)(s << 5);
            unsigned af[4][4];
#pragma unroll
            for (int mt = 0; mt < 4; mt++) ldsm4(af[mt], aAdr + (aoffB[mt] ^ sx));
#pragma unroll
            for (int p = 0; p < 2; p++) {
                unsigned bf[4];
                ldsm4(bf, bAdr + (boffB[p] ^ sx));
#pragma unroll
                for (int mt = 0; mt < 4; mt++) {
                    mma_bf16(c[mt][2 * p + 0], af[mt], bf + 0);
                    mma_bf16(c[mt][2 * p + 1], af[mt], bf + 2);
                }
            }
        }
    }

    // ---- epilogue: exp + masked reductions ----
    int tid_lo[4], tid_hi[4];
#pragma unroll
    for (int mt = 0; mt < 4; mt++) {
        tid_lo[mt] = tid[rowBase + wm * 64 + mt * 16 + g];
        tid_hi[mt] = tid[rowBase + wm * 64 + mt * 16 + g + 8];
    }

#pragma unroll
    for (int mt = 0; mt < 4; mt++) {
        const int r_lo = rowBase + wm * 64 + mt * 16 + g;
        const int r_hi = r_lo + 8;
        float tlo = 0.f, thi = 0.f, plo = 0.f, phi = 0.f;
#pragma unroll
        for (int nt = 0; nt < 4; nt++) {
            const int clA = wn * 32 + nt * 8 + 2 * tq;
            const int labA = labs[clA], labB = labs[clA + 1];
            const float e0 = __expf(c[mt][nt][0] * INV_TEMP);
            const float e1 = __expf(c[mt][nt][1] * INV_TEMP);
            const float e2 = __expf(c[mt][nt][2] * INV_TEMP);
            const float e3 = __expf(c[mt][nt][3] * INV_TEMP);
            tlo += e0 + e1;
            thi += e2 + e3;
            if (labA == tid_lo[mt]) plo += e0;
            if (labB == tid_lo[mt]) plo += e1;
            if (labA == tid_hi[mt]) phi += e2;
            if (labB == tid_hi[mt]) phi += e3;
            if (is_xx) {
                const int gcA = colBase - NY + clA;
                if (gcA == r_lo) g_diag[r_lo] = e0;
                if (gcA + 1 == r_lo) g_diag[r_lo] = e1;
                if (gcA == r_hi) g_diag[r_hi] = e2;
                if (gcA + 1 == r_hi) g_diag[r_hi] = e3;
            }
        }
#pragma unroll
        for (int off = 1; off < 4; off <<= 1) {
            tlo += __shfl_xor_sync(0xffffffffu, tlo, off);
            thi += __shfl_xor_sync(0xffffffffu, thi, off);
            plo += __shfl_xor_sync(0xffffffffu, plo, off);
            phi += __shfl_xor_sync(0xffffffffu, phi, off);
        }
        if (tq == 0) {
            float* dt = is_xx ? g_rxx_tot : g_rxy_tot;
            float* dp = is_xx ? g_rxx_pos : g_rxy_pos;
            atomicAdd(&dt[r_lo], tlo);
            atomicAdd(&dp[r_lo], plo);
            atomicAdd(&dt[r_hi], thi);
            atomicAdd(&dp[r_hi], phi);
        }
    }

    // ---- fused last-block finalize (threadFenceReduction pattern) ----
    __threadfence();
    __syncthreads();
    if (t == 0) lastFlag = (atomicAdd(&g_ctr, 1u) == NBLOCKS - 1) ? 1 : 0;
    __syncthreads();
    if (!lastFlag) return;
    // all 2303 other blocks have fenced their atomics before incrementing

    float* num_s = (float*)(dynsm);              // reuse dynamic smem
    float* den_s = num_s + T_TRACKS;
    int*   cnt_s = (int*)(den_s + T_TRACKS);
    num_s[t] = 0.f; den_s[t] = 0.f; cnt_s[t] = 0;
    __syncthreads();

    for (int i = t; i < N_ROWS; i += 256) {
        const int tr = tid[i];
        const float num_i = g_rxy_pos[i] + 0.5f * (g_rxx_pos[i] - g_diag[i]);
        const float den_i = (g_rxy_tot[i] - g_rxy_pos[i]) + (g_rxx_tot[i] - g_rxx_pos[i]);
        atomicAdd(&num_s[tr], num_i);
        atomicAdd(&den_s[tr], den_i);
        atomicAdd(&cnt_s[tr], 1);
    }
    __syncthreads();

    // self-clean for next graph replay (reads above complete)
    for (int i = t; i < N_ROWS; i += 256) {
        g_rxy_tot[i] = 0.f; g_rxy_pos[i] = 0.f;
        g_rxx_tot[i] = 0.f; g_rxx_pos[i] = 0.f;
    }
    if (t == 0) g_ctr = 0u;

    float loss = 0.f, pres = 0.f;
    if (cnt_s[t] > 0) {
        const float n = num_s[t];
        const float d = den_s[t];
        loss = -logf(n / (d + n));
        pres = 1.f;
    }
#pragma unroll
    for (int off = 16; off; off >>= 1) {
        loss += __shfl_xor_sync(0xffffffffu, loss, off);
        pres += __shfl_xor_sync(0xffffffffu, pres, off);
    }
    float* lsum = den_s + T_TRACKS + 64;   // reuse smem past cnt_s
    float* psum = lsum + 8;
    if ((t & 31) == 0) { lsum[t >> 5] = loss; psum[t >> 5] = pres; }
    __syncthreads();
    if (t == 0) {
        float L = 0.f, P = 0.f;
#pragma unroll
        for (int wi = 0; wi < 8; wi++) { L += lsum[wi]; P += psum[wi]; }
        out[0] = L / P;
    }
}

extern "C" void kernel_launch(void* const* d_in, const int* in_sizes, int n_in,
                              void* d_out, int out_size) {
    const float* x   = (const float*)d_in[0];
    const int*   tid = (const int*)d_in[1];
    const float* y   = (const float*)d_in[2];
    float* out = (float*)d_out;

    cudaFuncSetAttribute(sim_kernel, cudaFuncAttributeMaxDynamicSharedMemorySize, SMEM_DYN);
    conv_kernel<<<1152, 256>>>((const float4*)x, (const float4*)y);
    dim3 grid(N_ROWS / BM, NTOT / BN);   // 16 x 144
    sim_kernel<<<grid, 256, SMEM_DYN>>>(tid, out);
}

// round 15
// speedup vs baseline: 1.2265x; 1.2265x over previous
#include <cuda_runtime.h>
#include <cstdint>

#define N_ROWS   2048
#define DDIM     256
#define T_TRACKS 256
#define NY       16384
#define NTOT     18432
#define BM       128
#define BN       128
#define KC       64
#define NCH      (DDIM / KC)           // 4
#define NSTAGE   3
#define INV_TEMP (1.0f / 0.3f)

#define A_BYTES  (BM * 128)            // 16384
#define B_BYTES  (BN * 128)            // 16384
#define STAGE    (A_BYTES + B_BYTES)   // 32768
#define SMEM_DYN (NSTAGE * STAGE + 1024)   // 99328 -> 2 CTAs/SM

// Scratch (zero at module load; finalize self-cleans each replay)
__device__ float    g_rxy_tot[N_ROWS];
__device__ float    g_rxy_pos[N_ROWS];
__device__ float    g_rxx_tot[N_ROWS];
__device__ float    g_rxx_pos[N_ROWS];
__device__ float    g_diag[N_ROWS];
// bf16 copies of inputs (bf16x2 packed, k-contiguous), rebuilt every call
__device__ unsigned g_xb[N_ROWS * DDIM / 2];
__device__ unsigned g_yb[NY * DDIM / 2];

__device__ __forceinline__ uint32_t smem_u32(const void* p) {
    uint32_t a;
    asm("{ .reg .u64 t; cvta.to.shared.u64 t, %1; cvt.u32.u64 %0, t; }" : "=r"(a) : "l"(p));
    return a;
}
__device__ __forceinline__ unsigned pk(float hi, float lo) {
    unsigned r;
    asm("cvt.rn.bf16x2.f32 %0, %1, %2;" : "=r"(r) : "f"(hi), "f"(lo));
    return r;
}
__device__ __forceinline__ uint32_t swz(uint32_t off) {
    return off ^ ((off >> 3) & 0x70);
}
// .cg: L2-only path, bypasses L1 (reduces l1tex wavefront pressure)
__device__ __forceinline__ void cpasync16(uint32_t dst, const void* src) {
    asm volatile("cp.async.cg.shared.global [%0], [%1], 16;" :: "r"(dst), "l"(src));
}
#define CP_COMMIT() asm volatile("cp.async.commit_group;" ::: "memory")
#define CP_WAIT(N)  asm volatile("cp.async.wait_group %0;" :: "n"(N) : "memory")
__device__ __forceinline__ void ldsm4(unsigned* r, uint32_t addr) {
    asm volatile("ldmatrix.sync.aligned.m8n8.x4.shared.b16 {%0,%1,%2,%3}, [%4];"
                 : "=r"(r[0]), "=r"(r[1]), "=r"(r[2]), "=r"(r[3]) : "r"(addr));
}
__device__ __forceinline__ void mma_bf16(float* c, const unsigned* a, const unsigned* b) {
    asm volatile(
        "mma.sync.aligned.m16n8k16.row.col.f32.bf16.bf16.f32 "
        "{%0,%1,%2,%3}, {%4,%5,%6,%7}, {%8,%9}, {%0,%1,%2,%3};"
        : "+f"(c[0]), "+f"(c[1]), "+f"(c[2]), "+f"(c[3])
        : "r"(a[0]), "r"(a[1]), "r"(a[2]), "r"(a[3]), "r"(b[0]), "r"(b[1]));
}

// fp32 -> bf16x2: branch-free block partition, 4 independent float4 loads/thread
__global__ void conv_kernel(const float4* __restrict__ x4, const float4* __restrict__ y4) {
    int b = blockIdx.x;
    const float4* src;
    uint2* dst;
    if (b < 128) { src = x4; dst = (uint2*)g_xb; }
    else         { src = y4; dst = (uint2*)g_yb; b -= 128; }
    const int i0 = b * 1024 + threadIdx.x;
    float4 v[4];
#pragma unroll
    for (int k = 0; k < 4; k++) v[k] = src[i0 + k * 256];
#pragma unroll
    for (int k = 0; k < 4; k++) {
        uint2 r;
        r.x = pk(v[k].y, v[k].x);
        r.y = pk(v[k].w, v[k].z);
        dst[i0 + k * 256] = r;
    }
}

__global__ __launch_bounds__(256, 2) void sim_kernel(const int* __restrict__ tid) {
    extern __shared__ char dynsm[];
    __shared__ int labs[BN];

    const int t    = threadIdx.x;
    const int lane = t & 31;
    const int w    = t >> 5;        // 8 warps
    const int wm   = w >> 2;        // 0..1  (64 rows each)
    const int wn   = w & 3;         // 0..3  (32 cols each)
    const int g    = lane >> 2;     // 0..7
    const int tq   = lane & 3;      // 0..3

    const int rowBase = blockIdx.x * BM;
    const int colBase = blockIdx.y * BN;
    const bool is_xx  = (colBase >= NY);
    const char* asrc = (const char*)g_xb + (size_t)rowBase * 512;   // 512B per row
    const char* bsrc = is_xx ? ((const char*)g_xb + (size_t)(colBase - NY) * 512)
                             : ((const char*)g_yb + (size_t)colBase * 512);

    uint32_t sb  = smem_u32(dynsm);
    uint32_t pad = (1024u - (sb & 1023u)) & 1023u;
    const uint32_t baseAddr = sb + pad;

    if (t < BN) {   // labels for this tile's columns
        const int gcol = colBase + t;
        labs[t] = is_xx ? tid[gcol - NY] : (gcol & (T_TRACKS - 1));
    }

    // cp.async granule mapping: A and B each 1024 granules -> 4 per thread
    int arow_[4], akq_[4];
    uint32_t adst_[4];
#pragma unroll
    for (int i = 0; i < 4; i++) {
        const int idx = t + i * 256;
        arow_[i] = idx >> 3; akq_[i] = idx & 7;
        adst_[i] = swz((uint32_t)(arow_[i] * 128 + akq_[i] * 16));
    }

    auto issue_chunk = [&](int ch, int stg) {
        const uint32_t sA = baseAddr + stg * STAGE;
        const uint32_t sB = sA + A_BYTES;
#pragma unroll
        for (int i = 0; i < 4; i++)
            cpasync16(sA + adst_[i], asrc + (size_t)arow_[i] * 512 + ch * 128 + akq_[i] * 16);
#pragma unroll
        for (int i = 0; i < 4; i++)
            cpasync16(sB + adst_[i], bsrc + (size_t)arow_[i] * 512 + ch * 128 + akq_[i] * 16);
        CP_COMMIT();
    };

    // ldmatrix base offsets (s=0); k-step applied as XOR (s<<5) — exact under SW128
    uint32_t aoffB[4], boffB[2];
    {
        const int rA = lane & 15;
        const int kA = (lane >> 4) * 16;
#pragma unroll
        for (int mt = 0; mt < 4; mt++)
            aoffB[mt] = swz((uint32_t)((wm * 64 + mt * 16 + rA) * 128 + kA));
        const int rB = (lane & 7) + (lane >> 4) * 8;
        const int kB = ((lane >> 3) & 1) * 16;
#pragma unroll
        for (int p = 0; p < 2; p++)
            boffB[p] = swz((uint32_t)((wn * 32 + p * 16 + rB) * 128 + kB));
    }

    float c[4][4][4];
#pragma unroll
    for (int mt = 0; mt < 4; mt++)
#pragma unroll
        for (int nt = 0; nt < 4; nt++)
#pragma unroll
            for (int q = 0; q < 4; q++) c[mt][nt][q] = 0.f;

    issue_chunk(0, 0);
    issue_chunk(1, 1);

#pragma unroll
    for (int ch = 0; ch < NCH; ch++) {
        if (ch < NCH - 1) CP_WAIT(1); else CP_WAIT(0);
        __syncthreads();
        if (ch + 2 < NCH) issue_chunk(ch + 2, (ch + 2) % NSTAGE);

        const uint32_t aAdr = baseAddr + (ch % NSTAGE) * STAGE;
        const uint32_t bAdr = aAdr + A_BYTES;
#pragma unroll
        for (int s = 0; s < 4; s++) {
            const uint32_t sx = (uint32_t)(s << 5);
            unsigned af[4][4];
#pragma unroll
            for (int mt = 0; mt < 4; mt++) ldsm4(af[mt], aAdr + (aoffB[mt] ^ sx));
#pragma unroll
            for (int p = 0; p < 2; p++) {
                unsigned bf[4];
                ldsm4(bf, bAdr + (boffB[p] ^ sx));
#pragma unroll
                for (int mt = 0; mt < 4; mt++) {
                    mma_bf16(c[mt][2 * p + 0], af[mt], bf + 0);
                    mma_bf16(c[mt][2 * p + 1], af[mt], bf + 2);
                }
            }
        }
    }

    // ---- epilogue: exp + masked reductions ----
    int tid_lo[4], tid_hi[4];
#pragma unroll
    for (int mt = 0; mt < 4; mt++) {
        tid_lo[mt] = tid[rowBase + wm * 64 + mt * 16 + g];
        tid_hi[mt] = tid[rowBase + wm * 64 + mt * 16 + g + 8];
    }

#pragma unroll
    for (int mt = 0; mt < 4; mt++) {
        const int r_lo = rowBase + wm * 64 + mt * 16 + g;
        const int r_hi = r_lo + 8;
        float tlo = 0.f, thi = 0.f, plo = 0.f, phi = 0.f;
#pragma unroll
        for (int nt = 0; nt < 4; nt++) {
            const int clA = wn * 32 + nt * 8 + 2 * tq;
            const int labA = labs[clA], labB = labs[clA + 1];
            const float e0 = __expf(c[mt][nt][0] * INV_TEMP);
            const float e1 = __expf(c[mt][nt][1] * INV_TEMP);
            const float e2 = __expf(c[mt][nt][2] * INV_TEMP);
            const float e3 = __expf(c[mt][nt][3] * INV_TEMP);
            tlo += e0 + e1;
            thi += e2 + e3;
            if (labA == tid_lo[mt]) plo += e0;
            if (labB == tid_lo[mt]) plo += e1;
            if (labA == tid_hi[mt]) phi += e2;
            if (labB == tid_hi[mt]) phi += e3;
            if (is_xx) {
                const int gcA = colBase - NY + clA;
                if (gcA == r_lo) g_diag[r_lo] = e0;
                if (gcA + 1 == r_lo) g_diag[r_lo] = e1;
                if (gcA == r_hi) g_diag[r_hi] = e2;
                if (gcA + 1 == r_hi) g_diag[r_hi] = e3;
            }
        }
#pragma unroll
        for (int off = 1; off < 4; off <<= 1) {
            tlo += __shfl_xor_sync(0xffffffffu, tlo, off);
            thi += __shfl_xor_sync(0xffffffffu, thi, off);
            plo += __shfl_xor_sync(0xffffffffu, plo, off);
            phi += __shfl_xor_sync(0xffffffffu, phi, off);
        }
        if (tq == 0) {
            float* dt = is_xx ? g_rxx_tot : g_rxy_tot;
            float* dp = is_xx ? g_rxx_pos : g_rxy_pos;
            atomicAdd(&dt[r_lo], tlo);
            atomicAdd(&dp[r_lo], plo);
            atomicAdd(&dt[r_hi], thi);
            atomicAdd(&dp[r_hi], phi);
        }
    }
}

// Per-track segment sums + loss; self-cleans accumulators for next graph replay.
__global__ void finalize_kernel(const int* __restrict__ tid, float* __restrict__ out) {
    __shared__ float num_s[T_TRACKS];
    __shared__ float den_s[T_TRACKS];
    __shared__ int   cnt_s[T_TRACKS];
    __shared__ float lsum[32];
    __shared__ float psum[32];

    const int t = threadIdx.x;     // 1024 threads
    if (t < T_TRACKS) { num_s[t] = 0.f; den_s[t] = 0.f; cnt_s[t] = 0; }
    __syncthreads();

#pragma unroll
    for (int i = t; i < N_ROWS; i += 1024) {
        const int tr = tid[i];
        const float num_i = g_rxy_pos[i] + 0.5f * (g_rxx_pos[i] - g_diag[i]);
        const float den_i = (g_rxy_tot[i] - g_rxy_pos[i]) + (g_rxx_tot[i] - g_rxx_pos[i]);
        atomicAdd(&num_s[tr], num_i);
        atomicAdd(&den_s[tr], den_i);
        atomicAdd(&cnt_s[tr], 1);
    }
    __syncthreads();

    // self-clean for next graph replay
#pragma unroll
    for (int i = t; i < N_ROWS; i += 1024) {
        g_rxy_tot[i] = 0.f; g_rxy_pos[i] = 0.f;
        g_rxx_tot[i] = 0.f; g_rxx_pos[i] = 0.f;
    }

    float loss = 0.f, pres = 0.f;
    if (t < T_TRACKS && cnt_s[t] > 0) {
        const float n = num_s[t];
        const float d = den_s[t];
        loss = -logf(n / (d + n));
        pres = 1.f;
    }
#pragma unroll
    for (int off = 16; off; off >>= 1) {
        loss += __shfl_xor_sync(0xffffffffu, loss, off);
        pres += __shfl_xor_sync(0xffffffffu, pres, off);
    }
    if ((t & 31) == 0) { lsum[t >> 5] = loss; psum[t >> 5] = pres; }
    __syncthreads();
    if (t == 0) {
        float L = 0.f, P = 0.f;
#pragma unroll
        for (int wi = 0; wi < 32; wi++) { L += lsum[wi]; P += psum[wi]; }
        out[0] = L / P;
    }
}

extern "C" void kernel_launch(void* const* d_in, const int* in_sizes, int n_in,
                              void* d_out, int out_size) {
    const float* x   = (const float*)d_in[0];
    const int*   tid = (const int*)d_in[1];
    const float* y   = (const float*)d_in[2];
    float* out = (float*)d_out;

    cudaFuncSetAttribute(sim_kernel, cudaFuncAttributeMaxDynamicSharedMemorySize, SMEM_DYN);
    conv_kernel<<<1152, 256>>>((const float4*)x, (const float4*)y);
    dim3 grid(N_ROWS / BM, NTOT / BN);   // 16 x 144
    sim_kernel<<<grid, 256, SMEM_DYN>>>(tid);
    finalize_kernel<<<1, 1024>>>(tid, out);
}